// round 13
// baseline (speedup 1.0000x reference)
#include <cuda_runtime.h>
#include <math.h>
#include <stdint.h>

#define Bz  2
#define Tt  2048
#define Cc  2048
#define NH  32
#define NKV 8
#define HD  64
#define KVD (NKV * HD)   /* 512 */
#define BT  (Bz * Tt)    /* 4096 */

// Scratch (allocation-free rule: __device__ globals)
__device__ float g_q[(size_t)BT * Cc];
__device__ float g_k[(size_t)BT * KVD];
__device__ float g_v[(size_t)BT * KVD];
__device__ float g_attn[(size_t)BT * Cc];

// ---------------------------------------------------------------------------
// helpers
// ---------------------------------------------------------------------------
__device__ __forceinline__ float to_tf32(float x) {
    uint32_t r;
    asm("cvt.rna.tf32.f32 %0, %1;" : "=r"(r) : "f"(x));
    return __uint_as_float(r);
}
__device__ __forceinline__ float4 to_tf32_4(float4 v) {
    return make_float4(to_tf32(v.x), to_tf32(v.y), to_tf32(v.z), to_tf32(v.w));
}
__device__ __forceinline__ float4 to_tf32_4s(float4 v, float s) {
    return make_float4(to_tf32(v.x * s), to_tf32(v.y * s),
                       to_tf32(v.z * s), to_tf32(v.w * s));
}
__device__ __forceinline__ float ex2f(float x) {
    float r;
    asm("ex2.approx.f32 %0, %1;" : "=f"(r) : "f"(x));
    return r;
}

// D = A(16x8,row) @ B(8x8,col) + D, tf32 inputs (as b32), fp32 accum.
__device__ __forceinline__ void mma8(float c[4], const uint32_t a[4],
                                     uint32_t b0, uint32_t b1) {
    asm("mma.sync.aligned.m16n8k8.row.col.f32.tf32.tf32.f32 "
        "{%0,%1,%2,%3}, {%4,%5,%6,%7}, {%8,%9}, {%0,%1,%2,%3};\n"
        : "+f"(c[0]), "+f"(c[1]), "+f"(c[2]), "+f"(c[3])
        : "r"(a[0]), "r"(a[1]), "r"(a[2]), "r"(a[3]), "r"(b0), "r"(b1));
}

// ldmatrix x4 on 32-bit data (each 8x4-float quadrant viewed as 8x16B b16 mat).
__device__ __forceinline__ void ldsm4(uint32_t f[4], const float* p) {
    uint32_t a = (uint32_t)__cvta_generic_to_shared(p);
    asm("ldmatrix.sync.aligned.m8n8.x4.shared.b16 {%0,%1,%2,%3}, [%4];"
        : "=r"(f[0]), "=r"(f[1]), "=r"(f[2]), "=r"(f[3]) : "r"(a));
}
// A-pattern: f0=(g,t) f1=(g+8,t) f2=(g,t+4) f3=(g+8,t+4)  == mma A frag
#define AOFF(lane, S) (((((lane) >> 3) & 1) * 8 + ((lane) & 7)) * (S) + ((lane) >> 4) * 4)
// B-pattern: f0=b0(nt) f1=b1(nt) f2=b0(nt+1) f3=b1(nt+1)
#define BOFF(lane, S) ((((lane) >> 4) * 8 + ((lane) & 7)) * (S) + (((lane) >> 3) & 1) * 4)

// ---------------------------------------------------------------------------
// mma.sync tf32 GEMM, double-buffered, LDSM, 2 CTAs/SM.
// CTA tile 128x128, BK=32, 128 threads (4 warps), warp grid 2(M)x2(N),
// warp tile 64x64 (per-accumulator math identical to the 256-thread version
// -> bit-identical results). SMEM 72KB -> two CTAs co-reside per SM, so
// per-chunk barriers and prologue/epilogue tails of one CTA are covered by
// the other (previous config was 1 CTA/SM: every __syncthreads idled the SM).
// blockIdx.z selects (B0,C0)/(B1,C1) so K/V projections fuse into one launch.
// ---------------------------------------------------------------------------
#define GP 36
#define SMEM_GEMM ((2 * 128 + 2 * 128) * GP * 4)   /* 73728 B */

__global__ __launch_bounds__(128, 2) void gemm_mma(
    const float* __restrict__ A,
    const float* __restrict__ B0, float* __restrict__ C0,
    const float* __restrict__ B1, float* __restrict__ C1,
    int N, int K)
{
    extern __shared__ float sm[];
    float* As = sm;                    // [2][128][GP]
    float* Bs = sm + 2 * 128 * GP;     // [2][128][GP]

    const float* B = blockIdx.z ? B1 : B0;
    float*       C = blockIdx.z ? C1 : C0;

    const int tid  = threadIdx.x;
    const int wid  = tid >> 5;
    const int lane = tid & 31;
    const int gid  = lane >> 2;
    const int tig  = lane & 3;
    const int wm   = wid & 1;          // m base 64*wm
    const int wn   = wid >> 1;         // n base 64*wn
    const int aoff = AOFF(lane, GP);
    const int boff = BOFF(lane, GP);

    const float* Ab = A + (size_t)blockIdx.y * 128 * K;
    const float* Bb = B + (size_t)blockIdx.x * 128;

    const int bk = tid & 31, bn = (tid >> 5) * 32;

    float acc[4][8][4];
#pragma unroll
    for (int i = 0; i < 4; i++)
#pragma unroll
        for (int j = 0; j < 8; j++)
#pragma unroll
            for (int e = 0; e < 4; e++) acc[i][j][e] = 0.f;

    float4 a4[8], b4[8];
    const int NC = K >> 5;

#define LDG_A(k0)                                                              \
    do {                                                                       \
        const float* ap = Ab + (size_t)tid * K + (k0);                         \
        _Pragma("unroll")                                                      \
        for (int j = 0; j < 8; j++) a4[j] = *(const float4*)(ap + 4 * j);      \
    } while (0)

#define LDG_B(k0)                                                              \
    do {                                                                       \
        const float* bp = Bb + (size_t)((k0) + bk) * N + bn;                   \
        _Pragma("unroll")                                                      \
        for (int j = 0; j < 8; j++) b4[j] = *(const float4*)(bp + 4 * j);      \
    } while (0)

#define STS_A(st)                                                              \
    do {                                                                       \
        float* ad = As + ((st) * 128 + tid) * GP;                              \
        _Pragma("unroll")                                                      \
        for (int j = 0; j < 8; j++)                                            \
            *(float4*)(ad + 4 * j) = to_tf32_4(a4[j]);                         \
    } while (0)

#define STS_B(st)                                                              \
    do {                                                                       \
        const float* bf = (const float*)b4;                                    \
        _Pragma("unroll")                                                      \
        for (int e = 0; e < 32; e++)                                           \
            Bs[((st) * 128 + bn + e) * GP + bk] = to_tf32(bf[e]);              \
    } while (0)

#define COMPUTE_KS(st, ks)                                                     \
    do {                                                                       \
        uint32_t af[4][4], bfr[4][4];                                          \
        const float* Ast = As + (st) * 128 * GP + (ks) * 8;                    \
        const float* Bst = Bs + (st) * 128 * GP + (ks) * 8;                    \
        _Pragma("unroll")                                                      \
        for (int mt = 0; mt < 4; mt++)                                         \
            ldsm4(af[mt], Ast + (wm * 64 + mt * 16) * GP + aoff);              \
        _Pragma("unroll")                                                      \
        for (int np = 0; np < 4; np++)                                         \
            ldsm4(bfr[np], Bst + (wn * 64 + np * 16) * GP + boff);             \
        _Pragma("unroll")                                                      \
        for (int nt = 0; nt < 8; nt++)                                         \
            _Pragma("unroll")                                                  \
            for (int mt = 0; mt < 4; mt++)                                     \
                mma8(acc[mt][nt], af[mt],                                      \
                     bfr[nt >> 1][(nt & 1) * 2], bfr[nt >> 1][(nt & 1) * 2 + 1]); \
    } while (0)

    // prologue
    LDG_A(0); STS_A(0);
    LDG_B(0); STS_B(0);
    __syncthreads();

    for (int c = 0; c < NC; c++) {
        const int st = c & 1;
        const bool more = (c + 1 < NC);
        if (more) LDG_B((c + 1) * 32);
        COMPUTE_KS(st, 0);
        if (more) { STS_B(st ^ 1); LDG_A((c + 1) * 32); }
        COMPUTE_KS(st, 1);
        COMPUTE_KS(st, 2);
        if (more) STS_A(st ^ 1);
        COMPUTE_KS(st, 3);
        __syncthreads();
    }

    float* Cb = C + (size_t)blockIdx.y * 128 * N + blockIdx.x * 128;
#pragma unroll
    for (int mt = 0; mt < 4; mt++) {
        const int r0 = wm * 64 + mt * 16 + gid;
#pragma unroll
        for (int nt = 0; nt < 8; nt++) {
            const int cb = wn * 64 + nt * 8 + 2 * tig;
            *(float2*)(Cb + (size_t)r0 * N + cb) =
                make_float2(acc[mt][nt][0], acc[mt][nt][1]);
            *(float2*)(Cb + (size_t)(r0 + 8) * N + cb) =
                make_float2(acc[mt][nt][2], acc[mt][nt][3]);
        }
    }
}

// ---------------------------------------------------------------------------
// RoPE: one block per token row; 32 (cos,sin) pairs computed once in double.
// ---------------------------------------------------------------------------
__global__ __launch_bounds__(256) void rope2(float* __restrict__ q, float* __restrict__ k)
{
    const int row = blockIdx.x;          // 0..BT-1
    __shared__ float cs[32], sn[32];
    if (threadIdx.x < 32) {
        const int i = threadIdx.x;
        const double freq = exp2(-0.41524101186092028 * (double)i);
        const double ang  = (double)(row & (Tt - 1)) * freq;
        double s, c;
        sincos(ang, &s, &c);
        cs[i] = (float)c; sn[i] = (float)s;
    }
    __syncthreads();

    float2* qr = (float2*)(q + (size_t)row * Cc);
#pragma unroll
    for (int p = threadIdx.x; p < Cc / 2; p += 256) {
        const int i = p & 31;
        float2 v = qr[p];
        qr[p] = make_float2(v.x * cs[i] - v.y * sn[i],
                            v.x * sn[i] + v.y * cs[i]);
    }
    float2* kr = (float2*)(k + (size_t)row * KVD);
    {
        const int p = threadIdx.x;   // KVD/2 = 256 pairs, one per thread
        const int i = p & 31;
        float2 v = kr[p];
        kr[p] = make_float2(v.x * cs[i] - v.y * sn[i],
                            v.x * sn[i] + v.y * cs[i]);
    }
}

// ---------------------------------------------------------------------------
// Flash attention, mma.sync tf32, pipelined, LDSM, chain-free softmax.
// (REVERTED to the round-10 __syncthreads version: named barriers regressed.)
// ---------------------------------------------------------------------------
#define QT   256
#define PADA 68
#define SMEM_ATTN ((2 * QT + 4 * 64) * PADA * 4)   /* 208896 B */

__global__ __launch_bounds__(256, 1) void attn_mma(
    const float* __restrict__ Q, const float* __restrict__ K,
    const float* __restrict__ V, float* __restrict__ O)
{
    extern __shared__ float sm[];
    float* Qs = sm;                           // [QT][PADA]
    float* Ps = sm + QT * PADA;               // [QT][PADA]
    float* Ks = sm + 2 * QT * PADA;           // [2][64][PADA]
    float* Vs = Ks + 2 * 64 * PADA;           // [2][64][PADA]

    const int tid  = threadIdx.x;
    const int wid  = tid >> 5;                // 0..7
    const int lane = tid & 31;
    const int gid  = lane >> 2;
    const int tig  = lane & 3;
    const int aoff = AOFF(lane, PADA);
    const int boff = BOFF(lane, PADA);
    const int qtile = blockIdx.x, h = blockIdx.y, b = blockIdx.z;
    const int kvh  = h >> 2;

    const float* qbase = Q + (size_t)(b * Tt + qtile * QT) * Cc + h * HD;
    const float* kbase = K + (size_t)b * Tt * KVD + kvh * HD;
    const float* vbase = V + (size_t)b * Tt * KVD + kvh * HD;

    // stage Q scaled by log2e/8 (S comes out in log2 domain), tf32, STS.128
    {
        const float QSCALE = 1.4426950408889634f * 0.125f;
        const float* src = qbase + (size_t)tid * Cc;
        float* dst = Qs + tid * PADA;
#pragma unroll
        for (int j = 0; j < 16; j++)
            *(float4*)(dst + 4 * j) =
                to_tf32_4s(*(const float4*)(src + 4 * j), QSCALE);
    }

    const int r  = tid & 63;        // K/V row
    const int c0 = (tid >> 6) * 16; // d-chunk (4 chunks of 16)

    float4 k4[4], v4[4];
#define ATTN_LDG(kt)                                                           \
    do {                                                                       \
        const float* ksrc = kbase + (size_t)((kt) * 64 + r) * KVD + c0;        \
        const float* vsrc = vbase + (size_t)((kt) * 64 + r) * KVD + c0;        \
        _Pragma("unroll")                                                      \
        for (int j = 0; j < 4; j++) k4[j] = *(const float4*)(ksrc + 4 * j);    \
        _Pragma("unroll")                                                      \
        for (int j = 0; j < 4; j++) v4[j] = *(const float4*)(vsrc + 4 * j);    \
    } while (0)

#define ATTN_STS(st)                                                           \
    do {                                                                       \
        float* kd = Ks + ((st) * 64 + r) * PADA + c0;                          \
        _Pragma("unroll")                                                      \
        for (int j = 0; j < 4; j++)                                            \
            *(float4*)(kd + 4 * j) = to_tf32_4(k4[j]);                         \
        const float* vf = (const float*)v4;                                    \
        float* vb = Vs + (st) * 64 * PADA;                                     \
        _Pragma("unroll")                                                      \
        for (int e = 0; e < 16; e++)                                           \
            vb[(size_t)(c0 + e) * PADA + r] = to_tf32(vf[e]);                  \
    } while (0)

    // prologue: tile 0 staged into stage 0
    ATTN_LDG(0);
    ATTN_STS(0);

    float* Pw = Ps + (size_t)(32 * wid) * PADA;   // warp-private P slice

    float o[2][8][4];
#pragma unroll
    for (int mt = 0; mt < 2; mt++)
#pragma unroll
        for (int nt = 0; nt < 8; nt++)
#pragma unroll
            for (int e = 0; e < 4; e++) o[mt][nt][e] = 0.f;
    float lr[2][2];
#pragma unroll
    for (int mt = 0; mt < 2; mt++) { lr[mt][0] = 0.f; lr[mt][1] = 0.f; }
    __syncthreads();

    for (int kt = 0; kt < Tt / 64; kt++) {
        const int st = kt & 1;
        const bool more = (kt + 1 < Tt / 64);
        const float* Kst = Ks + st * 64 * PADA;
        const float* Vst = Vs + st * 64 * PADA;

        // S' = (Q*log2e/8) @ K^T  (LDSM operand loads)
        float s[2][8][4];
#pragma unroll
        for (int mt = 0; mt < 2; mt++)
#pragma unroll
            for (int nt = 0; nt < 8; nt++)
#pragma unroll
                for (int e = 0; e < 4; e++) s[mt][nt][e] = 0.f;
#pragma unroll
        for (int ks = 0; ks < 8; ks++) {
            uint32_t qa[2][4], kb[4][4];
            ldsm4(qa[0], Qs + (size_t)(32 * wid)      * PADA + ks * 8 + aoff);
            ldsm4(qa[1], Qs + (size_t)(32 * wid + 16) * PADA + ks * 8 + aoff);
#pragma unroll
            for (int np = 0; np < 4; np++)
                ldsm4(kb[np], Kst + (size_t)(np * 16) * PADA + ks * 8 + boff);
#pragma unroll
            for (int nt = 0; nt < 8; nt++) {
                const uint32_t b0 = kb[nt >> 1][(nt & 1) * 2];
                const uint32_t b1 = kb[nt >> 1][(nt & 1) * 2 + 1];
                mma8(s[0][nt], qa[0], b0, b1);
                mma8(s[1][nt], qa[1], b0, b1);
            }
        }

        // prefetch next tile's K/V (consumed by STS after PV)
        if (more) ATTN_LDG(kt + 1);

        // chain-free softmax numerator: P = 2^S', partial row sums only
#pragma unroll
        for (int mt = 0; mt < 2; mt++) {
            float* Pm = Pw + (size_t)(16 * mt) * PADA;
#pragma unroll
            for (int nt = 0; nt < 8; nt++) {
                const float p0 = ex2f(s[mt][nt][0]);
                const float p1 = ex2f(s[mt][nt][1]);
                const float p2 = ex2f(s[mt][nt][2]);
                const float p3 = ex2f(s[mt][nt][3]);
                lr[mt][0] += p0 + p1;
                lr[mt][1] += p2 + p3;
                const int cb = nt * 8 + 2 * tig;
                *(float2*)(Pm +  gid      * PADA + cb) =
                    make_float2(to_tf32(p0), to_tf32(p1));
                *(float2*)(Pm + (gid + 8) * PADA + cb) =
                    make_float2(to_tf32(p2), to_tf32(p3));
            }
        }
        __syncwarp();      // P visible within the warp

        // O += P @ V  (LDSM operand loads; V B-frags shared across m-tiles)
#pragma unroll
        for (int ks = 0; ks < 8; ks++) {
            uint32_t pa[2][4], vb[4][4];
            ldsm4(pa[0], Pw + ks * 8 + aoff);
            ldsm4(pa[1], Pw + (size_t)16 * PADA + ks * 8 + aoff);
#pragma unroll
            for (int np = 0; np < 4; np++)
                ldsm4(vb[np], Vst + (size_t)(np * 16) * PADA + ks * 8 + boff);
#pragma unroll
            for (int nt = 0; nt < 8; nt++) {
                const uint32_t b0 = vb[nt >> 1][(nt & 1) * 2];
                const uint32_t b1 = vb[nt >> 1][(nt & 1) * 2 + 1];
                mma8(o[0][nt], pa[0], b0, b1);
                mma8(o[1][nt], pa[1], b0, b1);
            }
        }

        // stage next tile into the idle buffer; single barrier per tile
        if (more) ATTN_STS(st ^ 1);
        __syncthreads();
    }

    // one-time row-sum reduction across the 4 tig lanes
#pragma unroll
    for (int mt = 0; mt < 2; mt++)
#pragma unroll
        for (int i = 0; i < 2; i++) {
            lr[mt][i] += __shfl_xor_sync(0xffffffffu, lr[mt][i], 1);
            lr[mt][i] += __shfl_xor_sync(0xffffffffu, lr[mt][i], 2);
        }

    // write O
#pragma unroll
    for (int mt = 0; mt < 2; mt++) {
        const float inv0 = 1.f / lr[mt][0], inv1 = 1.f / lr[mt][1];
        const size_t q0 = (size_t)(b * Tt + qtile * QT + 32 * wid + 16 * mt + gid);
#pragma unroll
        for (int nt = 0; nt < 8; nt++) {
            const int cb = h * HD + nt * 8 + 2 * tig;
            *(float2*)(O +  q0      * Cc + cb) =
                make_float2(o[mt][nt][0] * inv0, o[mt][nt][1] * inv0);
            *(float2*)(O + (q0 + 8) * Cc + cb) =
                make_float2(o[mt][nt][2] * inv1, o[mt][nt][3] * inv1);
        }
    }
}

// ---------------------------------------------------------------------------
extern "C" void kernel_launch(void* const* d_in, const int* in_sizes, int n_in,
                              void* d_out, int out_size)
{
    const float* x  = (const float*)d_in[0];
    const float* wq = (const float*)d_in[1];
    const float* wk = (const float*)d_in[2];
    const float* wv = (const float*)d_in[3];
    const float* wo = (const float*)d_in[4];
    float* out = (float*)d_out;

    float *qp, *kp, *vp, *ap;
    cudaGetSymbolAddress((void**)&qp, g_q);
    cudaGetSymbolAddress((void**)&kp, g_k);
    cudaGetSymbolAddress((void**)&vp, g_v);
    cudaGetSymbolAddress((void**)&ap, g_attn);

    cudaFuncSetAttribute(gemm_mma, cudaFuncAttributeMaxDynamicSharedMemorySize,
                         SMEM_GEMM);
    cudaFuncSetAttribute(attn_mma, cudaFuncAttributeMaxDynamicSharedMemorySize,
                         SMEM_ATTN);

    // Q projection (128x128 CTA tiles, 2 CTAs/SM)
    gemm_mma<<<dim3(Cc / 128, BT / 128, 1), 128, SMEM_GEMM>>>(
        x, wq, qp, wq, qp, Cc, Cc);
    // K + V projections fused into one full-chip launch (z selects pair)
    gemm_mma<<<dim3(KVD / 128, BT / 128, 2), 128, SMEM_GEMM>>>(
        x, wk, kp, wv, vp, KVD, Cc);

    // RoPE on q and k
    rope2<<<BT, 256>>>(qp, kp);

    // Attention (LDSM, chain-free softmax, single barrier per tile)
    attn_mma<<<dim3(Tt / QT, NH, Bz), 256, SMEM_ATTN>>>(qp, kp, vp, ap);

    // Output projection
    gemm_mma<<<dim3(Cc / 128, BT / 128, 1), 128, SMEM_GEMM>>>(
        ap, wo, out, wo, out, Cc, Cc);
}

// round 14
// speedup vs baseline: 1.0042x; 1.0042x over previous
#include <cuda_runtime.h>
#include <math.h>
#include <stdint.h>

#define Bz  2
#define Tt  2048
#define Cc  2048
#define NH  32
#define NKV 8
#define HD  64
#define KVD (NKV * HD)   /* 512 */
#define BT  (Bz * Tt)    /* 4096 */

// Scratch (allocation-free rule: __device__ globals)
__device__ float g_q[(size_t)BT * Cc];
__device__ float g_k[(size_t)BT * KVD];
__device__ float g_v[(size_t)BT * KVD];
__device__ float g_attn[(size_t)BT * Cc];

// ---------------------------------------------------------------------------
// helpers
// ---------------------------------------------------------------------------
__device__ __forceinline__ float to_tf32(float x) {
    uint32_t r;
    asm("cvt.rna.tf32.f32 %0, %1;" : "=r"(r) : "f"(x));
    return __uint_as_float(r);
}
__device__ __forceinline__ float4 to_tf32_4(float4 v) {
    return make_float4(to_tf32(v.x), to_tf32(v.y), to_tf32(v.z), to_tf32(v.w));
}
__device__ __forceinline__ float4 to_tf32_4s(float4 v, float s) {
    return make_float4(to_tf32(v.x * s), to_tf32(v.y * s),
                       to_tf32(v.z * s), to_tf32(v.w * s));
}
__device__ __forceinline__ float ex2f(float x) {
    float r;
    asm("ex2.approx.f32 %0, %1;" : "=f"(r) : "f"(x));
    return r;
}

// D = A(16x8,row) @ B(8x8,col) + D, tf32 inputs (as b32), fp32 accum.
__device__ __forceinline__ void mma8(float c[4], const uint32_t a[4],
                                     uint32_t b0, uint32_t b1) {
    asm("mma.sync.aligned.m16n8k8.row.col.f32.tf32.tf32.f32 "
        "{%0,%1,%2,%3}, {%4,%5,%6,%7}, {%8,%9}, {%0,%1,%2,%3};\n"
        : "+f"(c[0]), "+f"(c[1]), "+f"(c[2]), "+f"(c[3])
        : "r"(a[0]), "r"(a[1]), "r"(a[2]), "r"(a[3]), "r"(b0), "r"(b1));
}

// ldmatrix x4 on 32-bit data (each 8x4-float quadrant viewed as 8x16B b16 mat).
__device__ __forceinline__ void ldsm4(uint32_t f[4], const float* p) {
    uint32_t a = (uint32_t)__cvta_generic_to_shared(p);
    asm("ldmatrix.sync.aligned.m8n8.x4.shared.b16 {%0,%1,%2,%3}, [%4];"
        : "=r"(f[0]), "=r"(f[1]), "=r"(f[2]), "=r"(f[3]) : "r"(a));
}
// A-pattern: f0=(g,t) f1=(g+8,t) f2=(g,t+4) f3=(g+8,t+4)  == mma A frag
#define AOFF(lane, S) (((((lane) >> 3) & 1) * 8 + ((lane) & 7)) * (S) + ((lane) >> 4) * 4)
// B-pattern: f0=b0(nt) f1=b1(nt) f2=b0(nt+1) f3=b1(nt+1)
#define BOFF(lane, S) ((((lane) >> 4) * 8 + ((lane) & 7)) * (S) + (((lane) >> 3) & 1) * 4)

// ---------------------------------------------------------------------------
// mma.sync tf32 GEMM, double-buffered, LDSM (R10 shape: 256x128 CTA tile,
// 256 threads, warp grid 4(M)x2(N), warp tile 64x64), with two fixes:
//  * LDG->STS slack: both LDGs at chunk top; STS_A after 2 compute blocks
//    (~1024cyc slack), STS_B after all 4 (~2048cyc) - L2 latency under load
//    (250-600cyc) no longer leaks into the critical path each chunk.
//  * Multi-output launch: blockIdx.x spans up to three (B,C,N) column-tile
//    groups, so Q+K+V projections run as ONE launch (one wave-tail, not two).
// ---------------------------------------------------------------------------
#define GP 36
#define SMEM_GEMM ((2 * 256 + 2 * 128) * GP * 4)   /* 110592 B */

__global__ __launch_bounds__(256, 1) void gemm_mma(
    const float* __restrict__ A,
    const float* __restrict__ B0, float* __restrict__ C0, int n0, int t0,
    const float* __restrict__ B1, float* __restrict__ C1, int n1, int t1,
    const float* __restrict__ B2, float* __restrict__ C2, int n2,
    int K)
{
    extern __shared__ float sm[];
    float* As = sm;                    // [2][256][GP]
    float* Bs = sm + 2 * 256 * GP;     // [2][128][GP]

    // select output group from blockIdx.x
    const int xt = blockIdx.x;
    const float* B; float* C; int N, xi;
    if (xt < t0)           { B = B0; C = C0; N = n0; xi = xt; }
    else if (xt < t0 + t1) { B = B1; C = C1; N = n1; xi = xt - t0; }
    else                   { B = B2; C = C2; N = n2; xi = xt - t0 - t1; }

    const int tid  = threadIdx.x;
    const int wid  = tid >> 5;
    const int lane = tid & 31;
    const int gid  = lane >> 2;
    const int tig  = lane & 3;
    const int wm   = wid & 3;          // m base 64*wm
    const int wn   = wid >> 2;         // n base 64*wn
    const int aoff = AOFF(lane, GP);
    const int boff = BOFF(lane, GP);

    const float* Ab = A + (size_t)blockIdx.y * 256 * K;
    const float* Bb = B + (size_t)xi * 128;

    const int bk = tid & 31, bn = (tid >> 5) * 16;

    float acc[4][8][4];
#pragma unroll
    for (int i = 0; i < 4; i++)
#pragma unroll
        for (int j = 0; j < 8; j++)
#pragma unroll
            for (int e = 0; e < 4; e++) acc[i][j][e] = 0.f;

    float4 a4[8], b4[4];
    const int NC = K >> 5;

#define LDG_A(k0)                                                              \
    do {                                                                       \
        const float* ap = Ab + (size_t)tid * K + (k0);                         \
        _Pragma("unroll")                                                      \
        for (int j = 0; j < 8; j++) a4[j] = *(const float4*)(ap + 4 * j);      \
    } while (0)

#define LDG_B(k0)                                                              \
    do {                                                                       \
        const float* bp = Bb + (size_t)((k0) + bk) * N + bn;                   \
        _Pragma("unroll")                                                      \
        for (int j = 0; j < 4; j++) b4[j] = *(const float4*)(bp + 4 * j);      \
    } while (0)

#define STS_A(st)                                                              \
    do {                                                                       \
        float* ad = As + ((st) * 256 + tid) * GP;                              \
        _Pragma("unroll")                                                      \
        for (int j = 0; j < 8; j++)                                            \
            *(float4*)(ad + 4 * j) = to_tf32_4(a4[j]);                         \
    } while (0)

#define STS_B(st)                                                              \
    do {                                                                       \
        const float* bf = (const float*)b4;                                    \
        _Pragma("unroll")                                                      \
        for (int e = 0; e < 16; e++)                                           \
            Bs[((st) * 128 + bn + e) * GP + bk] = to_tf32(bf[e]);              \
    } while (0)

#define COMPUTE_KS(st, ks)                                                     \
    do {                                                                       \
        uint32_t af[4][4], bfr[4][4];                                          \
        const float* Ast = As + (st) * 256 * GP + (ks) * 8;                    \
        const float* Bst = Bs + (st) * 128 * GP + (ks) * 8;                    \
        _Pragma("unroll")                                                      \
        for (int mt = 0; mt < 4; mt++)                                         \
            ldsm4(af[mt], Ast + (wm * 64 + mt * 16) * GP + aoff);              \
        _Pragma("unroll")                                                      \
        for (int np = 0; np < 4; np++)                                         \
            ldsm4(bfr[np], Bst + (wn * 64 + np * 16) * GP + boff);             \
        _Pragma("unroll")                                                      \
        for (int nt = 0; nt < 8; nt++)                                         \
            _Pragma("unroll")                                                  \
            for (int mt = 0; mt < 4; mt++)                                     \
                mma8(acc[mt][nt], af[mt],                                      \
                     bfr[nt >> 1][(nt & 1) * 2], bfr[nt >> 1][(nt & 1) * 2 + 1]); \
    } while (0)

    // prologue
    LDG_A(0); LDG_B(0);
    STS_A(0); STS_B(0);
    __syncthreads();

    for (int c = 0; c < NC; c++) {
        const int st = c & 1;
        const bool more = (c + 1 < NC);
        if (more) { LDG_A((c + 1) * 32); LDG_B((c + 1) * 32); }
        COMPUTE_KS(st, 0);
        COMPUTE_KS(st, 1);
        if (more) STS_A(st ^ 1);
        COMPUTE_KS(st, 2);
        COMPUTE_KS(st, 3);
        if (more) STS_B(st ^ 1);
        __syncthreads();
    }

    float* Cb = C + (size_t)blockIdx.y * 256 * N + (size_t)xi * 128;
#pragma unroll
    for (int mt = 0; mt < 4; mt++) {
        const int r0 = wm * 64 + mt * 16 + gid;
#pragma unroll
        for (int nt = 0; nt < 8; nt++) {
            const int cb = wn * 64 + nt * 8 + 2 * tig;
            *(float2*)(Cb + (size_t)r0 * N + cb) =
                make_float2(acc[mt][nt][0], acc[mt][nt][1]);
            *(float2*)(Cb + (size_t)(r0 + 8) * N + cb) =
                make_float2(acc[mt][nt][2], acc[mt][nt][3]);
        }
    }
}

// ---------------------------------------------------------------------------
// RoPE: one block per token row; 32 (cos,sin) pairs computed once in double.
// ---------------------------------------------------------------------------
__global__ __launch_bounds__(256) void rope2(float* __restrict__ q, float* __restrict__ k)
{
    const int row = blockIdx.x;          // 0..BT-1
    __shared__ float cs[32], sn[32];
    if (threadIdx.x < 32) {
        const int i = threadIdx.x;
        const double freq = exp2(-0.41524101186092028 * (double)i);
        const double ang  = (double)(row & (Tt - 1)) * freq;
        double s, c;
        sincos(ang, &s, &c);
        cs[i] = (float)c; sn[i] = (float)s;
    }
    __syncthreads();

    float2* qr = (float2*)(q + (size_t)row * Cc);
#pragma unroll
    for (int p = threadIdx.x; p < Cc / 2; p += 256) {
        const int i = p & 31;
        float2 v = qr[p];
        qr[p] = make_float2(v.x * cs[i] - v.y * sn[i],
                            v.x * sn[i] + v.y * cs[i]);
    }
    float2* kr = (float2*)(k + (size_t)row * KVD);
    {
        const int p = threadIdx.x;   // KVD/2 = 256 pairs, one per thread
        const int i = p & 31;
        float2 v = kr[p];
        kr[p] = make_float2(v.x * cs[i] - v.y * sn[i],
                            v.x * sn[i] + v.y * cs[i]);
    }
}

// ---------------------------------------------------------------------------
// Flash attention, mma.sync tf32, pipelined, LDSM, chain-free softmax.
// (Unchanged from the best-measured round-10 version: 529us.)
// ---------------------------------------------------------------------------
#define QT   256
#define PADA 68
#define SMEM_ATTN ((2 * QT + 4 * 64) * PADA * 4)   /* 208896 B */

__global__ __launch_bounds__(256, 1) void attn_mma(
    const float* __restrict__ Q, const float* __restrict__ K,
    const float* __restrict__ V, float* __restrict__ O)
{
    extern __shared__ float sm[];
    float* Qs = sm;                           // [QT][PADA]
    float* Ps = sm + QT * PADA;               // [QT][PADA]
    float* Ks = sm + 2 * QT * PADA;           // [2][64][PADA]
    float* Vs = Ks + 2 * 64 * PADA;           // [2][64][PADA]

    const int tid  = threadIdx.x;
    const int wid  = tid >> 5;                // 0..7
    const int lane = tid & 31;
    const int gid  = lane >> 2;
    const int tig  = lane & 3;
    const int aoff = AOFF(lane, PADA);
    const int boff = BOFF(lane, PADA);
    const int qtile = blockIdx.x, h = blockIdx.y, b = blockIdx.z;
    const int kvh  = h >> 2;

    const float* qbase = Q + (size_t)(b * Tt + qtile * QT) * Cc + h * HD;
    const float* kbase = K + (size_t)b * Tt * KVD + kvh * HD;
    const float* vbase = V + (size_t)b * Tt * KVD + kvh * HD;

    // stage Q scaled by log2e/8 (S comes out in log2 domain), tf32, STS.128
    {
        const float QSCALE = 1.4426950408889634f * 0.125f;
        const float* src = qbase + (size_t)tid * Cc;
        float* dst = Qs + tid * PADA;
#pragma unroll
        for (int j = 0; j < 16; j++)
            *(float4*)(dst + 4 * j) =
                to_tf32_4s(*(const float4*)(src + 4 * j), QSCALE);
    }

    const int r  = tid & 63;        // K/V row
    const int c0 = (tid >> 6) * 16; // d-chunk (4 chunks of 16)

    float4 k4[4], v4[4];
#define ATTN_LDG(kt)                                                           \
    do {                                                                       \
        const float* ksrc = kbase + (size_t)((kt) * 64 + r) * KVD + c0;        \
        const float* vsrc = vbase + (size_t)((kt) * 64 + r) * KVD + c0;        \
        _Pragma("unroll")                                                      \
        for (int j = 0; j < 4; j++) k4[j] = *(const float4*)(ksrc + 4 * j);    \
        _Pragma("unroll")                                                      \
        for (int j = 0; j < 4; j++) v4[j] = *(const float4*)(vsrc + 4 * j);    \
    } while (0)

#define ATTN_STS(st)                                                           \
    do {                                                                       \
        float* kd = Ks + ((st) * 64 + r) * PADA + c0;                          \
        _Pragma("unroll")                                                      \
        for (int j = 0; j < 4; j++)                                            \
            *(float4*)(kd + 4 * j) = to_tf32_4(k4[j]);                         \
        const float* vf = (const float*)v4;                                    \
        float* vb = Vs + (st) * 64 * PADA;                                     \
        _Pragma("unroll")                                                      \
        for (int e = 0; e < 16; e++)                                           \
            vb[(size_t)(c0 + e) * PADA + r] = to_tf32(vf[e]);                  \
    } while (0)

    // prologue: tile 0 staged into stage 0
    ATTN_LDG(0);
    ATTN_STS(0);

    float* Pw = Ps + (size_t)(32 * wid) * PADA;   // warp-private P slice

    float o[2][8][4];
#pragma unroll
    for (int mt = 0; mt < 2; mt++)
#pragma unroll
        for (int nt = 0; nt < 8; nt++)
#pragma unroll
            for (int e = 0; e < 4; e++) o[mt][nt][e] = 0.f;
    float lr[2][2];
#pragma unroll
    for (int mt = 0; mt < 2; mt++) { lr[mt][0] = 0.f; lr[mt][1] = 0.f; }
    __syncthreads();

    for (int kt = 0; kt < Tt / 64; kt++) {
        const int st = kt & 1;
        const bool more = (kt + 1 < Tt / 64);
        const float* Kst = Ks + st * 64 * PADA;
        const float* Vst = Vs + st * 64 * PADA;

        // S' = (Q*log2e/8) @ K^T  (LDSM operand loads)
        float s[2][8][4];
#pragma unroll
        for (int mt = 0; mt < 2; mt++)
#pragma unroll
            for (int nt = 0; nt < 8; nt++)
#pragma unroll
                for (int e = 0; e < 4; e++) s[mt][nt][e] = 0.f;
#pragma unroll
        for (int ks = 0; ks < 8; ks++) {
            uint32_t qa[2][4], kb[4][4];
            ldsm4(qa[0], Qs + (size_t)(32 * wid)      * PADA + ks * 8 + aoff);
            ldsm4(qa[1], Qs + (size_t)(32 * wid + 16) * PADA + ks * 8 + aoff);
#pragma unroll
            for (int np = 0; np < 4; np++)
                ldsm4(kb[np], Kst + (size_t)(np * 16) * PADA + ks * 8 + boff);
#pragma unroll
            for (int nt = 0; nt < 8; nt++) {
                const uint32_t b0 = kb[nt >> 1][(nt & 1) * 2];
                const uint32_t b1 = kb[nt >> 1][(nt & 1) * 2 + 1];
                mma8(s[0][nt], qa[0], b0, b1);
                mma8(s[1][nt], qa[1], b0, b1);
            }
        }

        // prefetch next tile's K/V (consumed by STS after PV)
        if (more) ATTN_LDG(kt + 1);

        // chain-free softmax numerator: P = 2^S', partial row sums only
#pragma unroll
        for (int mt = 0; mt < 2; mt++) {
            float* Pm = Pw + (size_t)(16 * mt) * PADA;
#pragma unroll
            for (int nt = 0; nt < 8; nt++) {
                const float p0 = ex2f(s[mt][nt][0]);
                const float p1 = ex2f(s[mt][nt][1]);
                const float p2 = ex2f(s[mt][nt][2]);
                const float p3 = ex2f(s[mt][nt][3]);
                lr[mt][0] += p0 + p1;
                lr[mt][1] += p2 + p3;
                const int cb = nt * 8 + 2 * tig;
                *(float2*)(Pm +  gid      * PADA + cb) =
                    make_float2(to_tf32(p0), to_tf32(p1));
                *(float2*)(Pm + (gid + 8) * PADA + cb) =
                    make_float2(to_tf32(p2), to_tf32(p3));
            }
        }
        __syncwarp();      // P visible within the warp

        // O += P @ V  (LDSM operand loads; V B-frags shared across m-tiles)
#pragma unroll
        for (int ks = 0; ks < 8; ks++) {
            uint32_t pa[2][4], vb[4][4];
            ldsm4(pa[0], Pw + ks * 8 + aoff);
            ldsm4(pa[1], Pw + (size_t)16 * PADA + ks * 8 + aoff);
#pragma unroll
            for (int np = 0; np < 4; np++)
                ldsm4(vb[np], Vst + (size_t)(np * 16) * PADA + ks * 8 + boff);
#pragma unroll
            for (int nt = 0; nt < 8; nt++) {
                const uint32_t b0 = vb[nt >> 1][(nt & 1) * 2];
                const uint32_t b1 = vb[nt >> 1][(nt & 1) * 2 + 1];
                mma8(o[0][nt], pa[0], b0, b1);
                mma8(o[1][nt], pa[1], b0, b1);
            }
        }

        // stage next tile into the idle buffer; single barrier per tile
        if (more) ATTN_STS(st ^ 1);
        __syncthreads();
    }

    // one-time row-sum reduction across the 4 tig lanes
#pragma unroll
    for (int mt = 0; mt < 2; mt++)
#pragma unroll
        for (int i = 0; i < 2; i++) {
            lr[mt][i] += __shfl_xor_sync(0xffffffffu, lr[mt][i], 1);
            lr[mt][i] += __shfl_xor_sync(0xffffffffu, lr[mt][i], 2);
        }

    // write O
#pragma unroll
    for (int mt = 0; mt < 2; mt++) {
        const float inv0 = 1.f / lr[mt][0], inv1 = 1.f / lr[mt][1];
        const size_t q0 = (size_t)(b * Tt + qtile * QT + 32 * wid + 16 * mt + gid);
#pragma unroll
        for (int nt = 0; nt < 8; nt++) {
            const int cb = h * HD + nt * 8 + 2 * tig;
            *(float2*)(O +  q0      * Cc + cb) =
                make_float2(o[mt][nt][0] * inv0, o[mt][nt][1] * inv0);
            *(float2*)(O + (q0 + 8) * Cc + cb) =
                make_float2(o[mt][nt][2] * inv1, o[mt][nt][3] * inv1);
        }
    }
}

// ---------------------------------------------------------------------------
extern "C" void kernel_launch(void* const* d_in, const int* in_sizes, int n_in,
                              void* d_out, int out_size)
{
    const float* x  = (const float*)d_in[0];
    const float* wq = (const float*)d_in[1];
    const float* wk = (const float*)d_in[2];
    const float* wv = (const float*)d_in[3];
    const float* wo = (const float*)d_in[4];
    float* out = (float*)d_out;

    float *qp, *kp, *vp, *ap;
    cudaGetSymbolAddress((void**)&qp, g_q);
    cudaGetSymbolAddress((void**)&kp, g_k);
    cudaGetSymbolAddress((void**)&vp, g_v);
    cudaGetSymbolAddress((void**)&ap, g_attn);

    cudaFuncSetAttribute(gemm_mma, cudaFuncAttributeMaxDynamicSharedMemorySize,
                         SMEM_GEMM);
    cudaFuncSetAttribute(attn_mma, cudaFuncAttributeMaxDynamicSharedMemorySize,
                         SMEM_ATTN);

    // Q + K + V projections fused into ONE launch:
    // grid.x = 16 (wq tiles) + 4 (wk) + 4 (wv) = 24, grid.y = BT/256 = 16.
    gemm_mma<<<dim3(24, BT / 256), 256, SMEM_GEMM>>>(
        x,
        wq, qp, Cc,  16,
        wk, kp, KVD, 4,
        wv, vp, KVD,
        Cc);

    // RoPE on q and k
    rope2<<<BT, 256>>>(qp, kp);

    // Attention (LDSM, chain-free softmax, single barrier per tile)
    attn_mma<<<dim3(Tt / QT, NH, Bz), 256, SMEM_ATTN>>>(qp, kp, vp, ap);

    // Output projection (single group: 16 column tiles)
    gemm_mma<<<dim3(16, BT / 256), 256, SMEM_GEMM>>>(
        ap,
        wo, out, Cc, 16,
        wo, out, Cc, 0,
        wo, out, Cc,
        Cc);
}

// round 15
// speedup vs baseline: 1.1036x; 1.0990x over previous
#include <cuda_runtime.h>
#include <math.h>
#include <stdint.h>

#define Bz  2
#define Tt  2048
#define Cc  2048
#define NH  32
#define NKV 8
#define HD  64
#define KVD (NKV * HD)   /* 512 */
#define BT  (Bz * Tt)    /* 4096 */

// Scratch (allocation-free rule: __device__ globals)
__device__ float g_q[(size_t)BT * Cc];
__device__ float g_k[(size_t)BT * KVD];
__device__ float g_v[(size_t)BT * KVD];
__device__ float g_attn[(size_t)BT * Cc];
// tf32-pre-rounded inputs (weights also transposed to [N][K] k-major)
__device__ float g_xr[(size_t)BT * Cc];
__device__ float g_wqT[(size_t)Cc * Cc];
__device__ float g_wkT[(size_t)Cc * KVD];
__device__ float g_wvT[(size_t)Cc * KVD];
__device__ float g_woT[(size_t)Cc * Cc];

// ---------------------------------------------------------------------------
// helpers
// ---------------------------------------------------------------------------
__device__ __forceinline__ float to_tf32(float x) {
    uint32_t r;
    asm("cvt.rna.tf32.f32 %0, %1;" : "=r"(r) : "f"(x));
    return __uint_as_float(r);
}
__device__ __forceinline__ float4 to_tf32_4(float4 v) {
    return make_float4(to_tf32(v.x), to_tf32(v.y), to_tf32(v.z), to_tf32(v.w));
}
__device__ __forceinline__ float4 to_tf32_4s(float4 v, float s) {
    return make_float4(to_tf32(v.x * s), to_tf32(v.y * s),
                       to_tf32(v.z * s), to_tf32(v.w * s));
}
__device__ __forceinline__ float ex2f(float x) {
    float r;
    asm("ex2.approx.f32 %0, %1;" : "=f"(r) : "f"(x));
    return r;
}

// cp.async: 16B gmem->smem, L2-only path; per-thread commit/wait groups.
#define CPA(dst_u32, src_ptr) \
    asm volatile("cp.async.cg.shared.global [%0], [%1], 16;" \
                 :: "r"(dst_u32), "l"(src_ptr) : "memory")
#define CPC() asm volatile("cp.async.commit_group;" ::: "memory")
#define CPW(n) asm volatile("cp.async.wait_group %0;" :: "n"(n) : "memory")

// D = A(16x8,row) @ B(8x8,col) + D, tf32 inputs (as b32), fp32 accum.
__device__ __forceinline__ void mma8(float c[4], const uint32_t a[4],
                                     uint32_t b0, uint32_t b1) {
    asm("mma.sync.aligned.m16n8k8.row.col.f32.tf32.tf32.f32 "
        "{%0,%1,%2,%3}, {%4,%5,%6,%7}, {%8,%9}, {%0,%1,%2,%3};\n"
        : "+f"(c[0]), "+f"(c[1]), "+f"(c[2]), "+f"(c[3])
        : "r"(a[0]), "r"(a[1]), "r"(a[2]), "r"(a[3]), "r"(b0), "r"(b1));
}

// ldmatrix x4 on 32-bit data (each 8x4-float quadrant viewed as 8x16B b16 mat).
__device__ __forceinline__ void ldsm4(uint32_t f[4], const float* p) {
    uint32_t a = (uint32_t)__cvta_generic_to_shared(p);
    asm("ldmatrix.sync.aligned.m8n8.x4.shared.b16 {%0,%1,%2,%3}, [%4];"
        : "=r"(f[0]), "=r"(f[1]), "=r"(f[2]), "=r"(f[3]) : "r"(a));
}
// A-pattern: f0=(g,t) f1=(g+8,t) f2=(g,t+4) f3=(g+8,t+4)  == mma A frag
#define AOFF(lane, S) (((((lane) >> 3) & 1) * 8 + ((lane) & 7)) * (S) + ((lane) >> 4) * 4)
// B-pattern: f0=b0(nt) f1=b1(nt) f2=b0(nt+1) f3=b1(nt+1)
#define BOFF(lane, S) ((((lane) >> 4) * 8 + ((lane) & 7)) * (S) + (((lane) >> 3) & 1) * 4)

// ---------------------------------------------------------------------------
// cvt kernels: pre-round inputs to tf32 (rna) once, outside the GEMM loop.
//  cvt_tf32_k : elementwise copy+round (for x)
//  cvtT       : round + transpose [K][N] -> [N][K] (for weights; makes the
//               GEMM B staging a contiguous k-major cp.async)
// ---------------------------------------------------------------------------
__global__ void cvt_tf32_k(const float4* __restrict__ s, float4* __restrict__ d, int n4)
{
    int i = blockIdx.x * blockDim.x + threadIdx.x;
    if (i < n4) d[i] = to_tf32_4(s[i]);
}

__global__ void cvtT(const float* __restrict__ in, float* __restrict__ out,
                     int K, int N)
{
    __shared__ float t[32][33];
    const int k0 = blockIdx.y * 32, n0 = blockIdx.x * 32;
#pragma unroll
    for (int j = threadIdx.y; j < 32; j += 8)
        t[j][threadIdx.x] = to_tf32(in[(size_t)(k0 + j) * N + n0 + threadIdx.x]);
    __syncthreads();
#pragma unroll
    for (int j = threadIdx.y; j < 32; j += 8)
        out[(size_t)(n0 + j) * K + k0 + threadIdx.x] = t[threadIdx.x][j];
}

// ---------------------------------------------------------------------------
// cp.async tf32 GEMM. C[M,N] = A[M,K] @ BT[N,K]^T, inputs pre-rounded tf32.
// CTA tile 256x128, BK=32, 256 threads, warp grid 4(M)x2(N), warp tile 64x64
// (fragment values and mma order identical to previous rounds -> bit-identical
// results). THREE SMEM stages filled by cp.async (no staging registers, no
// thread STS): per chunk each thread issues 12 16B cp.async; wait_group(1) +
// one barrier per chunk gives ~2 chunks (~4000cyc) of landing slack, so L2
// latency never reaches the critical path.
// blockIdx.x spans up to three (B,C,N) groups: Q+K+V fuse into one launch.
// ---------------------------------------------------------------------------
#define GP 36
#define NST 3
#define SMEM_GEMM (NST * (256 + 128) * GP * 4)   /* 165888 B */

__global__ __launch_bounds__(256, 1) void gemm_cp(
    const float* __restrict__ A,
    const float* __restrict__ B0, float* __restrict__ C0, int n0, int t0,
    const float* __restrict__ B1, float* __restrict__ C1, int n1, int t1,
    const float* __restrict__ B2, float* __restrict__ C2, int n2,
    int K)
{
    extern __shared__ float sm[];
    float* As = sm;                    // [NST][256][GP]
    float* Bs = sm + NST * 256 * GP;   // [NST][128][GP]

    const int xt = blockIdx.x;
    const float* B; float* C; int N, xi;
    if (xt < t0)           { B = B0; C = C0; N = n0; xi = xt; }
    else if (xt < t0 + t1) { B = B1; C = C1; N = n1; xi = xt - t0; }
    else                   { B = B2; C = C2; N = n2; xi = xt - t0 - t1; }

    const int tid  = threadIdx.x;
    const int wid  = tid >> 5;
    const int lane = tid & 31;
    const int gid  = lane >> 2;
    const int tig  = lane & 3;
    const int wm   = wid & 3;          // m base 64*wm
    const int wn   = wid >> 2;         // n base 64*wn
    const int aoff = AOFF(lane, GP);
    const int boff = BOFF(lane, GP);

    const float* Ab = A + (size_t)blockIdx.y * 256 * K;
    const float* Bb = B + (size_t)xi * 128 * K;   // BT is [N][K] k-major

    const uint32_t As_u = (uint32_t)__cvta_generic_to_shared(As);
    const uint32_t Bs_u = (uint32_t)__cvta_generic_to_shared(Bs);

    // per-thread copy assignments
    const float* a_src = Ab + (size_t)tid * K;               // A row tid
    const uint32_t a_dst = As_u + (uint32_t)(tid * GP) * 4;
    const int brow = tid >> 1, bhalf = (tid & 1) * 16;       // B row, 16-f half
    const float* b_src = Bb + (size_t)brow * K + bhalf;
    const uint32_t b_dst = Bs_u + (uint32_t)(brow * GP + bhalf) * 4;

#define ISSUE(c, st)                                                           \
    do {                                                                       \
        const float* ap = a_src + (c) * 32;                                    \
        const uint32_t ad = a_dst + (uint32_t)((st) * 256 * GP) * 4;           \
        _Pragma("unroll")                                                      \
        for (int j = 0; j < 8; j++) CPA(ad + j * 16, ap + j * 4);              \
        const float* bp = b_src + (c) * 32;                                    \
        const uint32_t bd = b_dst + (uint32_t)((st) * 128 * GP) * 4;           \
        _Pragma("unroll")                                                      \
        for (int j = 0; j < 4; j++) CPA(bd + j * 16, bp + j * 4);              \
        CPC();                                                                 \
    } while (0)

#define COMPUTE_KS(st, ks)                                                     \
    do {                                                                       \
        uint32_t af[4][4], bfr[4][4];                                          \
        const float* Ast = As + (st) * 256 * GP + (ks) * 8;                    \
        const float* Bst = Bs + (st) * 128 * GP + (ks) * 8;                    \
        _Pragma("unroll")                                                      \
        for (int mt = 0; mt < 4; mt++)                                         \
            ldsm4(af[mt], Ast + (wm * 64 + mt * 16) * GP + aoff);              \
        _Pragma("unroll")                                                      \
        for (int np = 0; np < 4; np++)                                         \
            ldsm4(bfr[np], Bst + (wn * 64 + np * 16) * GP + boff);             \
        _Pragma("unroll")                                                      \
        for (int nt = 0; nt < 8; nt++)                                         \
            _Pragma("unroll")                                                  \
            for (int mt = 0; mt < 4; mt++)                                     \
                mma8(acc[mt][nt], af[mt],                                      \
                     bfr[nt >> 1][(nt & 1) * 2], bfr[nt >> 1][(nt & 1) * 2 + 1]); \
    } while (0)

    float acc[4][8][4];
#pragma unroll
    for (int i = 0; i < 4; i++)
#pragma unroll
        for (int j = 0; j < 8; j++)
#pragma unroll
            for (int e = 0; e < 4; e++) acc[i][j][e] = 0.f;

    const int NC = K >> 5;

    // prologue: chunks 0 and 1 in flight
    ISSUE(0, 0);
    ISSUE(1, 1);

    int st = 0;
    for (int c = 0; c < NC; c++) {
        if (c + 2 < NC) CPW(1); else CPW(0);
        __syncthreads();                 // chunk c visible to all warps;
                                         // stage (c+2)%3's readers all done
        if (c + 2 < NC) {
            int sn = st + 2; if (sn >= NST) sn -= NST;
            ISSUE(c + 2, sn);
        }
        COMPUTE_KS(st, 0);
        COMPUTE_KS(st, 1);
        COMPUTE_KS(st, 2);
        COMPUTE_KS(st, 3);
        if (++st == NST) st = 0;
    }

    float* Cb = C + (size_t)blockIdx.y * 256 * N + (size_t)xi * 128;
#pragma unroll
    for (int mt = 0; mt < 4; mt++) {
        const int r0 = wm * 64 + mt * 16 + gid;
#pragma unroll
        for (int nt = 0; nt < 8; nt++) {
            const int cb = wn * 64 + nt * 8 + 2 * tig;
            *(float2*)(Cb + (size_t)r0 * N + cb) =
                make_float2(acc[mt][nt][0], acc[mt][nt][1]);
            *(float2*)(Cb + (size_t)(r0 + 8) * N + cb) =
                make_float2(acc[mt][nt][2], acc[mt][nt][3]);
        }
    }
}

// ---------------------------------------------------------------------------
// RoPE: one block per token row; 32 (cos,sin) pairs computed once in double.
// ---------------------------------------------------------------------------
__global__ __launch_bounds__(256) void rope2(float* __restrict__ q, float* __restrict__ k)
{
    const int row = blockIdx.x;          // 0..BT-1
    __shared__ float cs[32], sn[32];
    if (threadIdx.x < 32) {
        const int i = threadIdx.x;
        const double freq = exp2(-0.41524101186092028 * (double)i);
        const double ang  = (double)(row & (Tt - 1)) * freq;
        double s, c;
        sincos(ang, &s, &c);
        cs[i] = (float)c; sn[i] = (float)s;
    }
    __syncthreads();

    float2* qr = (float2*)(q + (size_t)row * Cc);
#pragma unroll
    for (int p = threadIdx.x; p < Cc / 2; p += 256) {
        const int i = p & 31;
        float2 v = qr[p];
        qr[p] = make_float2(v.x * cs[i] - v.y * sn[i],
                            v.x * sn[i] + v.y * cs[i]);
    }
    float2* kr = (float2*)(k + (size_t)row * KVD);
    {
        const int p = threadIdx.x;   // KVD/2 = 256 pairs, one per thread
        const int i = p & 31;
        float2 v = kr[p];
        kr[p] = make_float2(v.x * cs[i] - v.y * sn[i],
                            v.x * sn[i] + v.y * cs[i]);
    }
}

// ---------------------------------------------------------------------------
// Flash attention (unchanged from best-measured round-10 version, 529us)
// EXCEPT the epilogue rounds its output to tf32: the wo GEMM no longer
// rounds its A operand, so rounding moves here -> same value bit-for-bit.
// ---------------------------------------------------------------------------
#define QT   256
#define PADA 68
#define SMEM_ATTN ((2 * QT + 4 * 64) * PADA * 4)   /* 208896 B */

__global__ __launch_bounds__(256, 1) void attn_mma(
    const float* __restrict__ Q, const float* __restrict__ K,
    const float* __restrict__ V, float* __restrict__ O)
{
    extern __shared__ float sm[];
    float* Qs = sm;                           // [QT][PADA]
    float* Ps = sm + QT * PADA;               // [QT][PADA]
    float* Ks = sm + 2 * QT * PADA;           // [2][64][PADA]
    float* Vs = Ks + 2 * 64 * PADA;           // [2][64][PADA]

    const int tid  = threadIdx.x;
    const int wid  = tid >> 5;                // 0..7
    const int lane = tid & 31;
    const int gid  = lane >> 2;
    const int tig  = lane & 3;
    const int aoff = AOFF(lane, PADA);
    const int boff = BOFF(lane, PADA);
    const int qtile = blockIdx.x, h = blockIdx.y, b = blockIdx.z;
    const int kvh  = h >> 2;

    const float* qbase = Q + (size_t)(b * Tt + qtile * QT) * Cc + h * HD;
    const float* kbase = K + (size_t)b * Tt * KVD + kvh * HD;
    const float* vbase = V + (size_t)b * Tt * KVD + kvh * HD;

    // stage Q scaled by log2e/8 (S comes out in log2 domain), tf32, STS.128
    {
        const float QSCALE = 1.4426950408889634f * 0.125f;
        const float* src = qbase + (size_t)tid * Cc;
        float* dst = Qs + tid * PADA;
#pragma unroll
        for (int j = 0; j < 16; j++)
            *(float4*)(dst + 4 * j) =
                to_tf32_4s(*(const float4*)(src + 4 * j), QSCALE);
    }

    const int r  = tid & 63;        // K/V row
    const int c0 = (tid >> 6) * 16; // d-chunk (4 chunks of 16)

    float4 k4[4], v4[4];
#define ATTN_LDG(kt)                                                           \
    do {                                                                       \
        const float* ksrc = kbase + (size_t)((kt) * 64 + r) * KVD + c0;        \
        const float* vsrc = vbase + (size_t)((kt) * 64 + r) * KVD + c0;        \
        _Pragma("unroll")                                                      \
        for (int j = 0; j < 4; j++) k4[j] = *(const float4*)(ksrc + 4 * j);    \
        _Pragma("unroll")                                                      \
        for (int j = 0; j < 4; j++) v4[j] = *(const float4*)(vsrc + 4 * j);    \
    } while (0)

#define ATTN_STS(st)                                                           \
    do {                                                                       \
        float* kd = Ks + ((st) * 64 + r) * PADA + c0;                          \
        _Pragma("unroll")                                                      \
        for (int j = 0; j < 4; j++)                                            \
            *(float4*)(kd + 4 * j) = to_tf32_4(k4[j]);                         \
        const float* vf = (const float*)v4;                                    \
        float* vb = Vs + (st) * 64 * PADA;                                     \
        _Pragma("unroll")                                                      \
        for (int e = 0; e < 16; e++)                                           \
            vb[(size_t)(c0 + e) * PADA + r] = to_tf32(vf[e]);                  \
    } while (0)

    // prologue: tile 0 staged into stage 0
    ATTN_LDG(0);
    ATTN_STS(0);

    float* Pw = Ps + (size_t)(32 * wid) * PADA;   // warp-private P slice

    float o[2][8][4];
#pragma unroll
    for (int mt = 0; mt < 2; mt++)
#pragma unroll
        for (int nt = 0; nt < 8; nt++)
#pragma unroll
            for (int e = 0; e < 4; e++) o[mt][nt][e] = 0.f;
    float lr[2][2];
#pragma unroll
    for (int mt = 0; mt < 2; mt++) { lr[mt][0] = 0.f; lr[mt][1] = 0.f; }
    __syncthreads();

    for (int kt = 0; kt < Tt / 64; kt++) {
        const int st = kt & 1;
        const bool more = (kt + 1 < Tt / 64);
        const float* Kst = Ks + st * 64 * PADA;
        const float* Vst = Vs + st * 64 * PADA;

        // S' = (Q*log2e/8) @ K^T  (LDSM operand loads)
        float s[2][8][4];
#pragma unroll
        for (int mt = 0; mt < 2; mt++)
#pragma unroll
            for (int nt = 0; nt < 8; nt++)
#pragma unroll
                for (int e = 0; e < 4; e++) s[mt][nt][e] = 0.f;
#pragma unroll
        for (int ks = 0; ks < 8; ks++) {
            uint32_t qa[2][4], kb[4][4];
            ldsm4(qa[0], Qs + (size_t)(32 * wid)      * PADA + ks * 8 + aoff);
            ldsm4(qa[1], Qs + (size_t)(32 * wid + 16) * PADA + ks * 8 + aoff);
#pragma unroll
            for (int np = 0; np < 4; np++)
                ldsm4(kb[np], Kst + (size_t)(np * 16) * PADA + ks * 8 + boff);
#pragma unroll
            for (int nt = 0; nt < 8; nt++) {
                const uint32_t b0 = kb[nt >> 1][(nt & 1) * 2];
                const uint32_t b1 = kb[nt >> 1][(nt & 1) * 2 + 1];
                mma8(s[0][nt], qa[0], b0, b1);
                mma8(s[1][nt], qa[1], b0, b1);
            }
        }

        // prefetch next tile's K/V (consumed by STS after PV)
        if (more) ATTN_LDG(kt + 1);

        // chain-free softmax numerator: P = 2^S', partial row sums only
#pragma unroll
        for (int mt = 0; mt < 2; mt++) {
            float* Pm = Pw + (size_t)(16 * mt) * PADA;
#pragma unroll
            for (int nt = 0; nt < 8; nt++) {
                const float p0 = ex2f(s[mt][nt][0]);
                const float p1 = ex2f(s[mt][nt][1]);
                const float p2 = ex2f(s[mt][nt][2]);
                const float p3 = ex2f(s[mt][nt][3]);
                lr[mt][0] += p0 + p1;
                lr[mt][1] += p2 + p3;
                const int cb = nt * 8 + 2 * tig;
                *(float2*)(Pm +  gid      * PADA + cb) =
                    make_float2(to_tf32(p0), to_tf32(p1));
                *(float2*)(Pm + (gid + 8) * PADA + cb) =
                    make_float2(to_tf32(p2), to_tf32(p3));
            }
        }
        __syncwarp();      // P visible within the warp

        // O += P @ V  (LDSM operand loads; V B-frags shared across m-tiles)
#pragma unroll
        for (int ks = 0; ks < 8; ks++) {
            uint32_t pa[2][4], vb[4][4];
            ldsm4(pa[0], Pw + ks * 8 + aoff);
            ldsm4(pa[1], Pw + (size_t)16 * PADA + ks * 8 + aoff);
#pragma unroll
            for (int np = 0; np < 4; np++)
                ldsm4(vb[np], Vst + (size_t)(np * 16) * PADA + ks * 8 + boff);
#pragma unroll
            for (int nt = 0; nt < 8; nt++) {
                const uint32_t b0 = vb[nt >> 1][(nt & 1) * 2];
                const uint32_t b1 = vb[nt >> 1][(nt & 1) * 2 + 1];
                mma8(o[0][nt], pa[0], b0, b1);
                mma8(o[1][nt], pa[1], b0, b1);
            }
        }

        // stage next tile into the idle buffer; single barrier per tile
        if (more) ATTN_STS(st ^ 1);
        __syncthreads();
    }

    // one-time row-sum reduction across the 4 tig lanes
#pragma unroll
    for (int mt = 0; mt < 2; mt++)
#pragma unroll
        for (int i = 0; i < 2; i++) {
            lr[mt][i] += __shfl_xor_sync(0xffffffffu, lr[mt][i], 1);
            lr[mt][i] += __shfl_xor_sync(0xffffffffu, lr[mt][i], 2);
        }

    // write O (tf32-rounded: feeds the wo GEMM directly)
#pragma unroll
    for (int mt = 0; mt < 2; mt++) {
        const float inv0 = 1.f / lr[mt][0], inv1 = 1.f / lr[mt][1];
        const size_t q0 = (size_t)(b * Tt + qtile * QT + 32 * wid + 16 * mt + gid);
#pragma unroll
        for (int nt = 0; nt < 8; nt++) {
            const int cb = h * HD + nt * 8 + 2 * tig;
            *(float2*)(O +  q0      * Cc + cb) =
                make_float2(to_tf32(o[mt][nt][0] * inv0), to_tf32(o[mt][nt][1] * inv0));
            *(float2*)(O + (q0 + 8) * Cc + cb) =
                make_float2(to_tf32(o[mt][nt][2] * inv1), to_tf32(o[mt][nt][3] * inv1));
        }
    }
}

// ---------------------------------------------------------------------------
extern "C" void kernel_launch(void* const* d_in, const int* in_sizes, int n_in,
                              void* d_out, int out_size)
{
    const float* x  = (const float*)d_in[0];
    const float* wq = (const float*)d_in[1];
    const float* wk = (const float*)d_in[2];
    const float* wv = (const float*)d_in[3];
    const float* wo = (const float*)d_in[4];
    float* out = (float*)d_out;

    float *qp, *kp, *vp, *ap, *xr, *wqT, *wkT, *wvT, *woT;
    cudaGetSymbolAddress((void**)&qp,  g_q);
    cudaGetSymbolAddress((void**)&kp,  g_k);
    cudaGetSymbolAddress((void**)&vp,  g_v);
    cudaGetSymbolAddress((void**)&ap,  g_attn);
    cudaGetSymbolAddress((void**)&xr,  g_xr);
    cudaGetSymbolAddress((void**)&wqT, g_wqT);
    cudaGetSymbolAddress((void**)&wkT, g_wkT);
    cudaGetSymbolAddress((void**)&wvT, g_wvT);
    cudaGetSymbolAddress((void**)&woT, g_woT);

    cudaFuncSetAttribute(gemm_cp, cudaFuncAttributeMaxDynamicSharedMemorySize,
                         SMEM_GEMM);
    cudaFuncSetAttribute(attn_mma, cudaFuncAttributeMaxDynamicSharedMemorySize,
                         SMEM_ATTN);

    // pre-round x; pre-round + transpose weights to [N][K]
    {
        const int n4 = (int)((size_t)BT * Cc / 4);
        cvt_tf32_k<<<(n4 + 255) / 256, 256>>>((const float4*)x, (float4*)xr, n4);
    }
    cvtT<<<dim3(Cc  / 32, Cc / 32), dim3(32, 8)>>>(wq, wqT, Cc, Cc);
    cvtT<<<dim3(KVD / 32, Cc / 32), dim3(32, 8)>>>(wk, wkT, Cc, KVD);
    cvtT<<<dim3(KVD / 32, Cc / 32), dim3(32, 8)>>>(wv, wvT, Cc, KVD);
    cvtT<<<dim3(Cc  / 32, Cc / 32), dim3(32, 8)>>>(wo, woT, Cc, Cc);

    // Q + K + V projections in ONE cp.async launch:
    // grid.x = 16 (wq tiles) + 4 (wk) + 4 (wv) = 24
    gemm_cp<<<dim3(24, BT / 256), 256, SMEM_GEMM>>>(
        xr,
        wqT, qp, Cc,  16,
        wkT, kp, KVD, 4,
        wvT, vp, KVD,
        Cc);

    // RoPE on q and k
    rope2<<<BT, 256>>>(qp, kp);

    // Attention (LDSM, chain-free softmax; epilogue rounds to tf32)
    attn_mma<<<dim3(Tt / QT, NH, Bz), 256, SMEM_ATTN>>>(qp, kp, vp, ap);

    // Output projection
    gemm_cp<<<dim3(16, BT / 256), 256, SMEM_GEMM>>>(
        ap,
        woT, out, Cc, 16,
        woT, out, Cc, 0,
        woT, out, Cc,
        Cc);
}

// round 16
// speedup vs baseline: 1.2058x; 1.0926x over previous
#include <cuda_runtime.h>
#include <math.h>
#include <stdint.h>

#define Bz  2
#define Tt  2048
#define Cc  2048
#define NH  32
#define NKV 8
#define HD  64
#define KVD (NKV * HD)   /* 512 */
#define BT  (Bz * Tt)    /* 4096 */

// Scratch (allocation-free rule: __device__ globals)
__device__ float g_q[(size_t)BT * Cc];
__device__ float g_k[(size_t)BT * KVD];
__device__ float g_v[(size_t)BT * KVD];
__device__ float g_attn[(size_t)BT * Cc];
// tf32-pre-rounded inputs (weights also transposed to [N][K] k-major)
__device__ float g_xr[(size_t)BT * Cc];
__device__ float g_wqT[(size_t)Cc * Cc];
__device__ float g_wkT[(size_t)Cc * KVD];
__device__ float g_wvT[(size_t)Cc * KVD];
__device__ float g_woT[(size_t)Cc * Cc];

// ---------------------------------------------------------------------------
// helpers
// ---------------------------------------------------------------------------
__device__ __forceinline__ float to_tf32(float x) {
    uint32_t r;
    asm("cvt.rna.tf32.f32 %0, %1;" : "=r"(r) : "f"(x));
    return __uint_as_float(r);
}
__device__ __forceinline__ float4 to_tf32_4(float4 v) {
    return make_float4(to_tf32(v.x), to_tf32(v.y), to_tf32(v.z), to_tf32(v.w));
}
__device__ __forceinline__ float4 to_tf32_4s(float4 v, float s) {
    return make_float4(to_tf32(v.x * s), to_tf32(v.y * s),
                       to_tf32(v.z * s), to_tf32(v.w * s));
}
__device__ __forceinline__ float ex2f(float x) {
    float r;
    asm("ex2.approx.f32 %0, %1;" : "=f"(r) : "f"(x));
    return r;
}

// cp.async: 16B gmem->smem, L2-only path; per-thread commit/wait groups.
#define CPA(dst_u32, src_ptr) \
    asm volatile("cp.async.cg.shared.global [%0], [%1], 16;" \
                 :: "r"(dst_u32), "l"(src_ptr) : "memory")
#define CPC() asm volatile("cp.async.commit_group;" ::: "memory")
#define CPW(n) asm volatile("cp.async.wait_group %0;" :: "n"(n) : "memory")

// D = A(16x8,row) @ B(8x8,col) + D, tf32 inputs (as b32), fp32 accum.
__device__ __forceinline__ void mma8(float c[4], const uint32_t a[4],
                                     uint32_t b0, uint32_t b1) {
    asm("mma.sync.aligned.m16n8k8.row.col.f32.tf32.tf32.f32 "
        "{%0,%1,%2,%3}, {%4,%5,%6,%7}, {%8,%9}, {%0,%1,%2,%3};\n"
        : "+f"(c[0]), "+f"(c[1]), "+f"(c[2]), "+f"(c[3])
        : "r"(a[0]), "r"(a[1]), "r"(a[2]), "r"(a[3]), "r"(b0), "r"(b1));
}

// ldmatrix x4 on 32-bit data (each 8x4-float quadrant viewed as 8x16B b16 mat).
__device__ __forceinline__ void ldsm4(uint32_t f[4], const float* p) {
    uint32_t a = (uint32_t)__cvta_generic_to_shared(p);
    asm("ldmatrix.sync.aligned.m8n8.x4.shared.b16 {%0,%1,%2,%3}, [%4];"
        : "=r"(f[0]), "=r"(f[1]), "=r"(f[2]), "=r"(f[3]) : "r"(a));
}
// A-pattern: f0=(g,t) f1=(g+8,t) f2=(g,t+4) f3=(g+8,t+4)  == mma A frag
#define AOFF(lane, S) (((((lane) >> 3) & 1) * 8 + ((lane) & 7)) * (S) + ((lane) >> 4) * 4)
// B-pattern: f0=b0(nt) f1=b1(nt) f2=b0(nt+1) f3=b1(nt+1)
#define BOFF(lane, S) ((((lane) >> 4) * 8 + ((lane) & 7)) * (S) + (((lane) >> 3) & 1) * 4)

// ---------------------------------------------------------------------------
// cvt kernels: pre-round inputs to tf32 (rna) once, outside the GEMM loop.
// ---------------------------------------------------------------------------
__global__ void cvt_tf32_k(const float4* __restrict__ s, float4* __restrict__ d, int n4)
{
    int i = blockIdx.x * blockDim.x + threadIdx.x;
    if (i < n4) d[i] = to_tf32_4(s[i]);
}

__global__ void cvtT(const float* __restrict__ in, float* __restrict__ out,
                     int K, int N)
{
    __shared__ float t[32][33];
    const int k0 = blockIdx.y * 32, n0 = blockIdx.x * 32;
#pragma unroll
    for (int j = threadIdx.y; j < 32; j += 8)
        t[j][threadIdx.x] = to_tf32(in[(size_t)(k0 + j) * N + n0 + threadIdx.x]);
    __syncthreads();
#pragma unroll
    for (int j = threadIdx.y; j < 32; j += 8)
        out[(size_t)(n0 + j) * K + k0 + threadIdx.x] = t[threadIdx.x][j];
}

// ---------------------------------------------------------------------------
// cp.async tf32 GEMM, 512 threads (16 warps = 4/SMSP). C = A @ BT^T.
// CTA tile 256x128 (UNCHANGED: same L2 traffic, same chunk count as the
// 256-thread version), warp grid 4(M)x4(N), warp tile 64x32. Per-SMSP mma
// floor per chunk is identical (4 warps x 64 mma x rt8 = 2048 cyc) but FOUR
// warps per scheduler now absorb the residual stalls that pinned issue=13%.
// acc shrinks 128->64 regs so 512 threads fit the 128-reg/thread cap.
// Per-output K-accumulation order unchanged -> bit-identical results.
// THREE cp.async stages; per chunk each thread issues 6 16B copies.
// blockIdx.x spans up to three (B,C,N) groups: Q+K+V fuse into one launch.
// ---------------------------------------------------------------------------
#define GP 36
#define NST 3
#define SMEM_GEMM (NST * (256 + 128) * GP * 4)   /* 165888 B */

__global__ __launch_bounds__(512, 1) void gemm_cp(
    const float* __restrict__ A,
    const float* __restrict__ B0, float* __restrict__ C0, int n0, int t0,
    const float* __restrict__ B1, float* __restrict__ C1, int n1, int t1,
    const float* __restrict__ B2, float* __restrict__ C2, int n2,
    int K)
{
    extern __shared__ float sm[];
    float* As = sm;                    // [NST][256][GP]
    float* Bs = sm + NST * 256 * GP;   // [NST][128][GP]

    const int xt = blockIdx.x;
    const float* B; float* C; int N, xi;
    if (xt < t0)           { B = B0; C = C0; N = n0; xi = xt; }
    else if (xt < t0 + t1) { B = B1; C = C1; N = n1; xi = xt - t0; }
    else                   { B = B2; C = C2; N = n2; xi = xt - t0 - t1; }

    const int tid  = threadIdx.x;
    const int wid  = tid >> 5;         // 0..15
    const int lane = tid & 31;
    const int gid  = lane >> 2;
    const int tig  = lane & 3;
    const int wm   = wid & 3;          // m base 64*wm
    const int wn   = wid >> 2;         // n base 32*wn
    const int aoff = AOFF(lane, GP);
    const int boff = BOFF(lane, GP);

    const float* Ab = A + (size_t)blockIdx.y * 256 * K;
    const float* Bb = B + (size_t)xi * 128 * K;   // BT is [N][K] k-major

    const uint32_t As_u = (uint32_t)__cvta_generic_to_shared(As);
    const uint32_t Bs_u = (uint32_t)__cvta_generic_to_shared(Bs);

    // per-thread copy assignments (512 threads)
    // A: 256 rows x 32 floats/chunk; thread t -> row t>>1, half (t&1)*16
    const float* a_src = Ab + (size_t)(tid >> 1) * K + (tid & 1) * 16;
    const uint32_t a_dst = As_u + (uint32_t)((tid >> 1) * GP + (tid & 1) * 16) * 4;
    // B: 128 rows x 32 floats/chunk; thread t -> row t>>2, quarter (t&3)*8
    const float* b_src = Bb + (size_t)(tid >> 2) * K + (tid & 3) * 8;
    const uint32_t b_dst = Bs_u + (uint32_t)((tid >> 2) * GP + (tid & 3) * 8) * 4;

#define ISSUE(c, st)                                                           \
    do {                                                                       \
        const float* ap = a_src + (c) * 32;                                    \
        const uint32_t ad = a_dst + (uint32_t)((st) * 256 * GP) * 4;           \
        _Pragma("unroll")                                                      \
        for (int j = 0; j < 4; j++) CPA(ad + j * 16, ap + j * 4);              \
        const float* bp = b_src + (c) * 32;                                    \
        const uint32_t bd = b_dst + (uint32_t)((st) * 128 * GP) * 4;           \
        _Pragma("unroll")                                                      \
        for (int j = 0; j < 2; j++) CPA(bd + j * 16, bp + j * 4);              \
        CPC();                                                                 \
    } while (0)

#define COMPUTE_KS(st, ks)                                                     \
    do {                                                                       \
        uint32_t af[4][4], bfr[2][4];                                          \
        const float* Ast = As + (st) * 256 * GP + (ks) * 8;                    \
        const float* Bst = Bs + (st) * 128 * GP + (ks) * 8;                    \
        _Pragma("unroll")                                                      \
        for (int mt = 0; mt < 4; mt++)                                         \
            ldsm4(af[mt], Ast + (wm * 64 + mt * 16) * GP + aoff);              \
        _Pragma("unroll")                                                      \
        for (int np = 0; np < 2; np++)                                         \
            ldsm4(bfr[np], Bst + (wn * 32 + np * 16) * GP + boff);             \
        _Pragma("unroll")                                                      \
        for (int nt = 0; nt < 4; nt++)                                         \
            _Pragma("unroll")                                                  \
            for (int mt = 0; mt < 4; mt++)                                     \
                mma8(acc[mt][nt], af[mt],                                      \
                     bfr[nt >> 1][(nt & 1) * 2], bfr[nt >> 1][(nt & 1) * 2 + 1]); \
    } while (0)

    float acc[4][4][4];
#pragma unroll
    for (int i = 0; i < 4; i++)
#pragma unroll
        for (int j = 0; j < 4; j++)
#pragma unroll
            for (int e = 0; e < 4; e++) acc[i][j][e] = 0.f;

    const int NC = K >> 5;

    // prologue: chunks 0 and 1 in flight
    ISSUE(0, 0);
    ISSUE(1, 1);

    int st = 0;
    for (int c = 0; c < NC; c++) {
        if (c + 2 < NC) CPW(1); else CPW(0);
        __syncthreads();                 // chunk c visible; stage (c+2)%3 free
        if (c + 2 < NC) {
            int sn = st + 2; if (sn >= NST) sn -= NST;
            ISSUE(c + 2, sn);
        }
        COMPUTE_KS(st, 0);
        COMPUTE_KS(st, 1);
        COMPUTE_KS(st, 2);
        COMPUTE_KS(st, 3);
        if (++st == NST) st = 0;
    }

    float* Cb = C + (size_t)blockIdx.y * 256 * N + (size_t)xi * 128;
#pragma unroll
    for (int mt = 0; mt < 4; mt++) {
        const int r0 = wm * 64 + mt * 16 + gid;
#pragma unroll
        for (int nt = 0; nt < 4; nt++) {
            const int cb = wn * 32 + nt * 8 + 2 * tig;
            *(float2*)(Cb + (size_t)r0 * N + cb) =
                make_float2(acc[mt][nt][0], acc[mt][nt][1]);
            *(float2*)(Cb + (size_t)(r0 + 8) * N + cb) =
                make_float2(acc[mt][nt][2], acc[mt][nt][3]);
        }
    }
}

// ---------------------------------------------------------------------------
// RoPE: one block per token row; 32 (cos,sin) pairs computed once in double.
// ---------------------------------------------------------------------------
__global__ __launch_bounds__(256) void rope2(float* __restrict__ q, float* __restrict__ k)
{
    const int row = blockIdx.x;          // 0..BT-1
    __shared__ float cs[32], sn[32];
    if (threadIdx.x < 32) {
        const int i = threadIdx.x;
        const double freq = exp2(-0.41524101186092028 * (double)i);
        const double ang  = (double)(row & (Tt - 1)) * freq;
        double s, c;
        sincos(ang, &s, &c);
        cs[i] = (float)c; sn[i] = (float)s;
    }
    __syncthreads();

    float2* qr = (float2*)(q + (size_t)row * Cc);
#pragma unroll
    for (int p = threadIdx.x; p < Cc / 2; p += 256) {
        const int i = p & 31;
        float2 v = qr[p];
        qr[p] = make_float2(v.x * cs[i] - v.y * sn[i],
                            v.x * sn[i] + v.y * cs[i]);
    }
    float2* kr = (float2*)(k + (size_t)row * KVD);
    {
        const int p = threadIdx.x;   // KVD/2 = 256 pairs, one per thread
        const int i = p & 31;
        float2 v = kr[p];
        kr[p] = make_float2(v.x * cs[i] - v.y * sn[i],
                            v.x * sn[i] + v.y * cs[i]);
    }
}

// ---------------------------------------------------------------------------
// Flash attention (unchanged; epilogue rounds to tf32 for the wo GEMM).
// ---------------------------------------------------------------------------
#define QT   256
#define PADA 68
#define SMEM_ATTN ((2 * QT + 4 * 64) * PADA * 4)   /* 208896 B */

__global__ __launch_bounds__(256, 1) void attn_mma(
    const float* __restrict__ Q, const float* __restrict__ K,
    const float* __restrict__ V, float* __restrict__ O)
{
    extern __shared__ float sm[];
    float* Qs = sm;                           // [QT][PADA]
    float* Ps = sm + QT * PADA;               // [QT][PADA]
    float* Ks = sm + 2 * QT * PADA;           // [2][64][PADA]
    float* Vs = Ks + 2 * 64 * PADA;           // [2][64][PADA]

    const int tid  = threadIdx.x;
    const int wid  = tid >> 5;                // 0..7
    const int lane = tid & 31;
    const int gid  = lane >> 2;
    const int tig  = lane & 3;
    const int aoff = AOFF(lane, PADA);
    const int boff = BOFF(lane, PADA);
    const int qtile = blockIdx.x, h = blockIdx.y, b = blockIdx.z;
    const int kvh  = h >> 2;

    const float* qbase = Q + (size_t)(b * Tt + qtile * QT) * Cc + h * HD;
    const float* kbase = K + (size_t)b * Tt * KVD + kvh * HD;
    const float* vbase = V + (size_t)b * Tt * KVD + kvh * HD;

    // stage Q scaled by log2e/8 (S comes out in log2 domain), tf32, STS.128
    {
        const float QSCALE = 1.4426950408889634f * 0.125f;
        const float* src = qbase + (size_t)tid * Cc;
        float* dst = Qs + tid * PADA;
#pragma unroll
        for (int j = 0; j < 16; j++)
            *(float4*)(dst + 4 * j) =
                to_tf32_4s(*(const float4*)(src + 4 * j), QSCALE);
    }

    const int r  = tid & 63;        // K/V row
    const int c0 = (tid >> 6) * 16; // d-chunk (4 chunks of 16)

    float4 k4[4], v4[4];
#define ATTN_LDG(kt)                                                           \
    do {                                                                       \
        const float* ksrc = kbase + (size_t)((kt) * 64 + r) * KVD + c0;        \
        const float* vsrc = vbase + (size_t)((kt) * 64 + r) * KVD + c0;        \
        _Pragma("unroll")                                                      \
        for (int j = 0; j < 4; j++) k4[j] = *(const float4*)(ksrc + 4 * j);    \
        _Pragma("unroll")                                                      \
        for (int j = 0; j < 4; j++) v4[j] = *(const float4*)(vsrc + 4 * j);    \
    } while (0)

#define ATTN_STS(st)                                                           \
    do {                                                                       \
        float* kd = Ks + ((st) * 64 + r) * PADA + c0;                          \
        _Pragma("unroll")                                                      \
        for (int j = 0; j < 4; j++)                                            \
            *(float4*)(kd + 4 * j) = to_tf32_4(k4[j]);                         \
        const float* vf = (const float*)v4;                                    \
        float* vb = Vs + (st) * 64 * PADA;                                     \
        _Pragma("unroll")                                                      \
        for (int e = 0; e < 16; e++)                                           \
            vb[(size_t)(c0 + e) * PADA + r] = to_tf32(vf[e]);                  \
    } while (0)

    // prologue: tile 0 staged into stage 0
    ATTN_LDG(0);
    ATTN_STS(0);

    float* Pw = Ps + (size_t)(32 * wid) * PADA;   // warp-private P slice

    float o[2][8][4];
#pragma unroll
    for (int mt = 0; mt < 2; mt++)
#pragma unroll
        for (int nt = 0; nt < 8; nt++)
#pragma unroll
            for (int e = 0; e < 4; e++) o[mt][nt][e] = 0.f;
    float lr[2][2];
#pragma unroll
    for (int mt = 0; mt < 2; mt++) { lr[mt][0] = 0.f; lr[mt][1] = 0.f; }
    __syncthreads();

    for (int kt = 0; kt < Tt / 64; kt++) {
        const int st = kt & 1;
        const bool more = (kt + 1 < Tt / 64);
        const float* Kst = Ks + st * 64 * PADA;
        const float* Vst = Vs + st * 64 * PADA;

        // S' = (Q*log2e/8) @ K^T  (LDSM operand loads)
        float s[2][8][4];
#pragma unroll
        for (int mt = 0; mt < 2; mt++)
#pragma unroll
            for (int nt = 0; nt < 8; nt++)
#pragma unroll
                for (int e = 0; e < 4; e++) s[mt][nt][e] = 0.f;
#pragma unroll
        for (int ks = 0; ks < 8; ks++) {
            uint32_t qa[2][4], kb[4][4];
            ldsm4(qa[0], Qs + (size_t)(32 * wid)      * PADA + ks * 8 + aoff);
            ldsm4(qa[1], Qs + (size_t)(32 * wid + 16) * PADA + ks * 8 + aoff);
#pragma unroll
            for (int np = 0; np < 4; np++)
                ldsm4(kb[np], Kst + (size_t)(np * 16) * PADA + ks * 8 + boff);
#pragma unroll
            for (int nt = 0; nt < 8; nt++) {
                const uint32_t b0 = kb[nt >> 1][(nt & 1) * 2];
                const uint32_t b1 = kb[nt >> 1][(nt & 1) * 2 + 1];
                mma8(s[0][nt], qa[0], b0, b1);
                mma8(s[1][nt], qa[1], b0, b1);
            }
        }

        // prefetch next tile's K/V (consumed by STS after PV)
        if (more) ATTN_LDG(kt + 1);

        // chain-free softmax numerator: P = 2^S', partial row sums only
#pragma unroll
        for (int mt = 0; mt < 2; mt++) {
            float* Pm = Pw + (size_t)(16 * mt) * PADA;
#pragma unroll
            for (int nt = 0; nt < 8; nt++) {
                const float p0 = ex2f(s[mt][nt][0]);
                const float p1 = ex2f(s[mt][nt][1]);
                const float p2 = ex2f(s[mt][nt][2]);
                const float p3 = ex2f(s[mt][nt][3]);
                lr[mt][0] += p0 + p1;
                lr[mt][1] += p2 + p3;
                const int cb = nt * 8 + 2 * tig;
                *(float2*)(Pm +  gid      * PADA + cb) =
                    make_float2(to_tf32(p0), to_tf32(p1));
                *(float2*)(Pm + (gid + 8) * PADA + cb) =
                    make_float2(to_tf32(p2), to_tf32(p3));
            }
        }
        __syncwarp();      // P visible within the warp

        // O += P @ V  (LDSM operand loads; V B-frags shared across m-tiles)
#pragma unroll
        for (int ks = 0; ks < 8; ks++) {
            uint32_t pa[2][4], vb[4][4];
            ldsm4(pa[0], Pw + ks * 8 + aoff);
            ldsm4(pa[1], Pw + (size_t)16 * PADA + ks * 8 + aoff);
#pragma unroll
            for (int np = 0; np < 4; np++)
                ldsm4(vb[np], Vst + (size_t)(np * 16) * PADA + ks * 8 + boff);
#pragma unroll
            for (int nt = 0; nt < 8; nt++) {
                const uint32_t b0 = vb[nt >> 1][(nt & 1) * 2];
                const uint32_t b1 = vb[nt >> 1][(nt & 1) * 2 + 1];
                mma8(o[0][nt], pa[0], b0, b1);
                mma8(o[1][nt], pa[1], b0, b1);
            }
        }

        // stage next tile into the idle buffer; single barrier per tile
        if (more) ATTN_STS(st ^ 1);
        __syncthreads();
    }

    // one-time row-sum reduction across the 4 tig lanes
#pragma unroll
    for (int mt = 0; mt < 2; mt++)
#pragma unroll
        for (int i = 0; i < 2; i++) {
            lr[mt][i] += __shfl_xor_sync(0xffffffffu, lr[mt][i], 1);
            lr[mt][i] += __shfl_xor_sync(0xffffffffu, lr[mt][i], 2);
        }

    // write O (tf32-rounded: feeds the wo GEMM directly)
#pragma unroll
    for (int mt = 0; mt < 2; mt++) {
        const float inv0 = 1.f / lr[mt][0], inv1 = 1.f / lr[mt][1];
        const size_t q0 = (size_t)(b * Tt + qtile * QT + 32 * wid + 16 * mt + gid);
#pragma unroll
        for (int nt = 0; nt < 8; nt++) {
            const int cb = h * HD + nt * 8 + 2 * tig;
            *(float2*)(O +  q0      * Cc + cb) =
                make_float2(to_tf32(o[mt][nt][0] * inv0), to_tf32(o[mt][nt][1] * inv0));
            *(float2*)(O + (q0 + 8) * Cc + cb) =
                make_float2(to_tf32(o[mt][nt][2] * inv1), to_tf32(o[mt][nt][3] * inv1));
        }
    }
}

// ---------------------------------------------------------------------------
extern "C" void kernel_launch(void* const* d_in, const int* in_sizes, int n_in,
                              void* d_out, int out_size)
{
    const float* x  = (const float*)d_in[0];
    const float* wq = (const float*)d_in[1];
    const float* wk = (const float*)d_in[2];
    const float* wv = (const float*)d_in[3];
    const float* wo = (const float*)d_in[4];
    float* out = (float*)d_out;

    float *qp, *kp, *vp, *ap, *xr, *wqT, *wkT, *wvT, *woT;
    cudaGetSymbolAddress((void**)&qp,  g_q);
    cudaGetSymbolAddress((void**)&kp,  g_k);
    cudaGetSymbolAddress((void**)&vp,  g_v);
    cudaGetSymbolAddress((void**)&ap,  g_attn);
    cudaGetSymbolAddress((void**)&xr,  g_xr);
    cudaGetSymbolAddress((void**)&wqT, g_wqT);
    cudaGetSymbolAddress((void**)&wkT, g_wkT);
    cudaGetSymbolAddress((void**)&wvT, g_wvT);
    cudaGetSymbolAddress((void**)&woT, g_woT);

    cudaFuncSetAttribute(gemm_cp, cudaFuncAttributeMaxDynamicSharedMemorySize,
                         SMEM_GEMM);
    cudaFuncSetAttribute(attn_mma, cudaFuncAttributeMaxDynamicSharedMemorySize,
                         SMEM_ATTN);

    // pre-round x; pre-round + transpose weights to [N][K]
    {
        const int n4 = (int)((size_t)BT * Cc / 4);
        cvt_tf32_k<<<(n4 + 255) / 256, 256>>>((const float4*)x, (float4*)xr, n4);
    }
    cvtT<<<dim3(Cc  / 32, Cc / 32), dim3(32, 8)>>>(wq, wqT, Cc, Cc);
    cvtT<<<dim3(KVD / 32, Cc / 32), dim3(32, 8)>>>(wk, wkT, Cc, KVD);
    cvtT<<<dim3(KVD / 32, Cc / 32), dim3(32, 8)>>>(wv, wvT, Cc, KVD);
    cvtT<<<dim3(Cc  / 32, Cc / 32), dim3(32, 8)>>>(wo, woT, Cc, Cc);

    // Q + K + V projections in ONE cp.async launch (512 threads/CTA):
    // grid.x = 16 (wq tiles) + 4 (wk) + 4 (wv) = 24
    gemm_cp<<<dim3(24, BT / 256), 512, SMEM_GEMM>>>(
        xr,
        wqT, qp, Cc,  16,
        wkT, kp, KVD, 4,
        wvT, vp, KVD,
        Cc);

    // RoPE on q and k
    rope2<<<BT, 256>>>(qp, kp);

    // Attention (LDSM, chain-free softmax; epilogue rounds to tf32)
    attn_mma<<<dim3(Tt / QT, NH, Bz), 256, SMEM_ATTN>>>(qp, kp, vp, ap);

    // Output projection
    gemm_cp<<<dim3(16, BT / 256), 512, SMEM_GEMM>>>(
        ap,
        woT, out, Cc, 16,
        woT, out, Cc, 0,
        woT, out, Cc,
        Cc);
}